// round 2
// baseline (speedup 1.0000x reference)
#include <cuda_runtime.h>

#define BN 1024
#define CN 128
#define DN 16
#define SN 4
#define K3N 23
#define K2N 5
#define K1N 2
#define ON 4   // total output irrep rows: 1 (0e) + 3 (1o)
#define NB 8   // nodes per batch in main kernel

// ---------------- static device scratch (no runtime allocation) ----------------
__device__ float g_uw3[(size_t)SN * CN * ON * DN * DN * DN]; // 8,388,608 floats = 32 MiB
__device__ float g_uw2[SN * CN * ON * DN * DN];              // 524,288 floats
__device__ float g_uw1[SN * CN * ON * DN];                   // 32,768 floats
__device__ float g_y[(size_t)BN * CN * ON];                  // 524,288 floats
__device__ int   g_bucket[SN * BN];
__device__ int   g_cnt[SN];

// ---------------- kernel 1: bucket nodes by species ----------------
__global__ void bucket_kernel(const int* __restrict__ sp) {
    __shared__ int scnt[SN];
    int t = threadIdx.x;                 // exactly BN threads
    if (t < SN) scnt[t] = 0;
    __syncthreads();
    int e = sp[t];
    int pos = atomicAdd(&scnt[e], 1);
    g_bucket[e * BN + pos] = t;
    __syncthreads();
    if (t < SN) g_cnt[t] = scnt[t];
}

// ---------------- kernel 2: uw3[e,c,o,i,j,l] = sum_k u3[o,i,j,l,k] * w3[t,e,k,c] ----------------
// grid: 256 blocks = (e, o, i); 256 threads = (j, l); each thread loops c.
__global__ void uw3_kernel(const float* __restrict__ u3_0,
                           const float* __restrict__ u3_1,
                           const float* __restrict__ w3) {
    int bx = blockIdx.x;
    int e = bx >> 6;
    int o = (bx >> 4) & 3;
    int i = bx & 15;
    int t = threadIdx.x;

    __shared__ float u3s[DN * DN * K3N];   // 5888 floats
    __shared__ float w3s[K3N * CN];        // 2944 floats

    const float* u3src = (o == 0)
        ? (u3_0 + (size_t)(i * DN * DN) * K3N)
        : (u3_1 + (size_t)(((o - 1) * DN + i) * DN * DN) * K3N);
    for (int idx = t; idx < DN * DN * K3N; idx += 256) u3s[idx] = u3src[idx];

    int tt = (o > 0);
    const float* w3src = w3 + (size_t)(tt * SN + e) * K3N * CN;
    for (int idx = t; idx < K3N * CN; idx += 256) w3s[idx] = w3src[idx];
    __syncthreads();

    int j = t >> 4, l = t & 15;
    float u3r[K3N];
#pragma unroll
    for (int k = 0; k < K3N; k++) u3r[k] = u3s[(j * DN + l) * K3N + k];

    int jl = (i * DN + j) * DN + l;
    for (int c = 0; c < CN; c++) {
        float acc = 0.f;
#pragma unroll
        for (int k = 0; k < K3N; k++) acc = fmaf(u3r[k], w3s[k * CN + c], acc);
        g_uw3[((size_t)((e * CN + c) * ON + o)) * (DN * DN * DN) + jl] = acc;
    }
}

// ---------------- kernel 3: uw2 / uw1 precompute ----------------
__global__ void uw21_kernel(const float* __restrict__ u2_0, const float* __restrict__ u2_1,
                            const float* __restrict__ u1_0, const float* __restrict__ u1_1,
                            const float* __restrict__ w2,   const float* __restrict__ w1) {
    int t = blockIdx.x * blockDim.x + threadIdx.x;
    const int N2 = SN * CN * ON * DN * DN;   // 524288
    const int N1 = SN * CN * ON * DN;        // 32768
    if (t < N2) {
        int j = t & 15, i = (t >> 4) & 15, o = (t >> 8) & 3, c = (t >> 10) & 127, e = t >> 17;
        int tt = (o > 0);
        const float* u2 = (o == 0) ? (u2_0 + (i * 16 + j) * K2N)
                                   : (u2_1 + (((o - 1) * 16 + i) * 16 + j) * K2N);
        float acc = 0.f;
#pragma unroll
        for (int k = 0; k < K2N; k++)
            acc = fmaf(u2[k], w2[((tt * SN + e) * K2N + k) * CN + c], acc);
        g_uw2[t] = acc;
    } else if (t < N2 + N1) {
        int t2 = t - N2;
        int i = t2 & 15, o = (t2 >> 4) & 3, c = (t2 >> 6) & 127, e = t2 >> 13;
        int tt = (o > 0);
        const float* u1 = (o == 0) ? (u1_0 + i * K1N)
                                   : (u1_1 + ((o - 1) * 16 + i) * K1N);
        float acc = 0.f;
#pragma unroll
        for (int k = 0; k < K1N; k++)
            acc = fmaf(u1[k], w1[((tt * SN + e) * K1N + k) * CN + c], acc);
        g_uw1[t2] = acc;
    }
}

// ---------------- kernel 4: main contraction ----------------
// grid = 2*S*C blocks; block = (e, c, node-half). 1024 threads = (o,i,j).
// Each thread keeps uw3[o,i,j,0..15] in registers for the whole node loop.
__global__ void __launch_bounds__(1024, 1) main_kernel(const float* __restrict__ x) {
    int bx = blockIdx.x;
    int half = bx & 1;
    int pair = bx >> 1;
    int e = pair >> 7;          // pair / CN
    int c = pair & 127;         // pair % CN

    int tid = threadIdx.x;
    int o = tid >> 8, i = (tid >> 4) & 15, j = tid & 15;
    int w = tid >> 5, lane = tid & 31;

    size_t base_ec = (size_t)((e * CN + c) * ON + o);
    const float4* up = (const float4*)(g_uw3 + (base_ec * 256 + (size_t)(i * 16 + j)) * 16);
    float4 a0 = up[0], a1 = up[1], a2 = up[2], a3 = up[3];
    float uw2r = g_uw2[base_ec * 256 + i * 16 + j];
    float uw1r = g_uw1[base_ec * 16 + i];

    __shared__ float xs[NB][16];
    __shared__ float part[NB][32];
    __shared__ int   nbs[NB];

    int cnt = g_cnt[e];
    int h = (cnt + 1) >> 1;
    int start = half ? h : 0;
    int end   = half ? cnt : h;
    const int* bucket = g_bucket + e * BN;

    for (int nb = start; nb < end; nb += NB) {
        int rem = end - nb; if (rem > NB) rem = NB;
        __syncthreads();  // protect nbs/part from previous iteration's readers
        if (tid < NB * 16) {
            int nn = tid >> 4, l = tid & 15;
            if (nn < rem) {
                int b = bucket[nb + nn];
                if (l == 0) nbs[nn] = b;
                xs[nn][l] = x[((size_t)b * CN + c) * 16 + l];
            }
        }
        __syncthreads();

        float contrib[NB];
#pragma unroll
        for (int nn = 0; nn < NB; nn++) {
            const float4* xv = (const float4*)xs[nn];
            float4 x0 = xv[0], x1 = xv[1], x2 = xv[2], x3 = xv[3];
            float v = uw2r;
            v = fmaf(a0.x, x0.x, v); v = fmaf(a0.y, x0.y, v);
            v = fmaf(a0.z, x0.z, v); v = fmaf(a0.w, x0.w, v);
            v = fmaf(a1.x, x1.x, v); v = fmaf(a1.y, x1.y, v);
            v = fmaf(a1.z, x1.z, v); v = fmaf(a1.w, x1.w, v);
            v = fmaf(a2.x, x2.x, v); v = fmaf(a2.y, x2.y, v);
            v = fmaf(a2.z, x2.z, v); v = fmaf(a2.w, x2.w, v);
            v = fmaf(a3.x, x3.x, v); v = fmaf(a3.y, x3.y, v);
            v = fmaf(a3.z, x3.z, v); v = fmaf(a3.w, x3.w, v);
            float xi = xs[nn][i], xj = xs[nn][j];
            float extra = (j == 0) ? xi * uw1r : 0.0f;
            contrib[nn] = fmaf(xi * xj, v, extra);
        }

#pragma unroll
        for (int nn = 0; nn < NB; nn++) {
            float s = contrib[nn];
            s += __shfl_xor_sync(0xffffffffu, s, 16);
            s += __shfl_xor_sync(0xffffffffu, s, 8);
            s += __shfl_xor_sync(0xffffffffu, s, 4);
            s += __shfl_xor_sync(0xffffffffu, s, 2);
            s += __shfl_xor_sync(0xffffffffu, s, 1);
            if (lane == 0) part[nn][w] = s;
        }
        __syncthreads();

        if (tid < NB * 4) {
            int nn = tid >> 2, oo = tid & 3;
            if (nn < rem) {
                float s = 0.f;
                const float* pp = part[nn] + oo * 8;
#pragma unroll
                for (int ww = 0; ww < 8; ww++) s += pp[ww];
                g_y[((size_t)nbs[nn] * CN + c) * ON + oo] = s;
            }
        }
    }
}

// ---------------- kernel 5: equivariant linear + output flatten ----------------
// out[b, 0:C]            = (1/sqrt(C)) * sum_c y[b,c,0]   * w_lin[0][c,n]
// out[b, C + n*3 + o']   = (1/sqrt(C)) * sum_c y[b,c,1+o']* w_lin[1][c,n]
__global__ void final_kernel(const float* __restrict__ w_lin, float* __restrict__ out) {
    int b = blockIdx.x;
    int s = threadIdx.x;                    // 512 threads
    __shared__ float ys[CN * ON];
    ys[s] = g_y[(size_t)b * (CN * ON) + s];
    __syncthreads();

    int t, n, oo;
    if (s < CN) { t = 0; n = s; oo = 0; }
    else {
        int r = s - CN;
        t = 1; n = r / 3; oo = 1 + (r - (r / 3) * 3);
    }
    const float* wl = w_lin + (size_t)t * CN * CN + n;
    float acc = 0.f;
#pragma unroll 8
    for (int c = 0; c < CN; c++) acc = fmaf(ys[c * ON + oo], wl[(size_t)c * CN], acc);
    out[(size_t)b * (CN * ON) + s] = acc * 0.08838834764831845f; // 1/sqrt(128)
}

// ---------------- launch ----------------
extern "C" void kernel_launch(void* const* d_in, const int* in_sizes, int n_in,
                              void* d_out, int out_size) {
    const float* x    = (const float*)d_in[0];
    const float* u3_0 = (const float*)d_in[1];
    const float* u3_1 = (const float*)d_in[2];
    const float* u2_0 = (const float*)d_in[3];
    const float* u2_1 = (const float*)d_in[4];
    const float* u1_0 = (const float*)d_in[5];
    const float* u1_1 = (const float*)d_in[6];
    const float* w3   = (const float*)d_in[7];
    const float* w2   = (const float*)d_in[8];
    const float* w1   = (const float*)d_in[9];
    const float* wlin = (const float*)d_in[10];
    const int*   sp   = (const int*)d_in[11];

    bucket_kernel<<<1, BN>>>(sp);
    uw3_kernel<<<SN * ON * DN, 256>>>(u3_0, u3_1, w3);
    {
        int total = SN * CN * ON * DN * DN + SN * CN * ON * DN;
        uw21_kernel<<<(total + 255) / 256, 256>>>(u2_0, u2_1, u1_0, u1_1, w2, w1);
    }
    main_kernel<<<2 * SN * CN, 1024>>>(x);
    final_kernel<<<BN, CN * ON>>>(wlin, (float*)d_out);
}

// round 4
// speedup vs baseline: 1.1430x; 1.1430x over previous
#include <cuda_runtime.h>

#define BN 1024
#define CN 128
#define DN 16
#define SN 4
#define K3N 23
#define K2N 5
#define K1N 2
#define ON 4   // total output irrep rows: 1 (0e) + 3 (1o)
#define NB 8   // nodes per batch in main kernel
#define SPLIT 4 // node-range splits per (e,c)

// ---------------- static device scratch (no runtime allocation) ----------------
__device__ float g_uw3[(size_t)SN * CN * ON * DN * DN * DN]; // 32 MiB
__device__ float g_uw2[SN * CN * ON * DN * DN];
__device__ float g_uw1[SN * CN * ON * DN];
__device__ float g_y[(size_t)BN * CN * ON];
__device__ int   g_bucket[SN * BN];
__device__ int   g_cnt[SN];

// ---------------- kernel 1: bucket nodes by species ----------------
__global__ void bucket_kernel(const int* __restrict__ sp) {
    __shared__ int scnt[SN];
    int t = threadIdx.x;                 // exactly BN threads
    if (t < SN) scnt[t] = 0;
    __syncthreads();
    int e = sp[t];
    int pos = atomicAdd(&scnt[e], 1);
    g_bucket[e * BN + pos] = t;
    __syncthreads();
    if (t < SN) g_cnt[t] = scnt[t];
}

// ---------------- kernel 2: uw3[e,c,o,i,j,l] = sum_k u3[o,i,j,l,k] * w3[t,e,k,c] ----------------
__global__ void uw3_kernel(const float* __restrict__ u3_0,
                           const float* __restrict__ u3_1,
                           const float* __restrict__ w3) {
    int bx = blockIdx.x;
    int e = bx >> 6;
    int o = (bx >> 4) & 3;
    int i = bx & 15;
    int t = threadIdx.x;

    __shared__ float u3s[DN * DN * K3N];
    __shared__ float w3s[K3N * CN];

    const float* u3src = (o == 0)
        ? (u3_0 + (size_t)(i * DN * DN) * K3N)
        : (u3_1 + (size_t)(((o - 1) * DN + i) * DN * DN) * K3N);
    for (int idx = t; idx < DN * DN * K3N; idx += 256) u3s[idx] = u3src[idx];

    int tt = (o > 0);
    const float* w3src = w3 + (size_t)(tt * SN + e) * K3N * CN;
    for (int idx = t; idx < K3N * CN; idx += 256) w3s[idx] = w3src[idx];
    __syncthreads();

    int j = t >> 4, l = t & 15;
    float u3r[K3N];
#pragma unroll
    for (int k = 0; k < K3N; k++) u3r[k] = u3s[(j * DN + l) * K3N + k];

    int jl = (i * DN + j) * DN + l;
    for (int c = 0; c < CN; c++) {
        float acc = 0.f;
#pragma unroll
        for (int k = 0; k < K3N; k++) acc = fmaf(u3r[k], w3s[k * CN + c], acc);
        g_uw3[((size_t)((e * CN + c) * ON + o)) * (DN * DN * DN) + jl] = acc;
    }
}

// ---------------- kernel 3: uw2 / uw1 precompute ----------------
__global__ void uw21_kernel(const float* __restrict__ u2_0, const float* __restrict__ u2_1,
                            const float* __restrict__ u1_0, const float* __restrict__ u1_1,
                            const float* __restrict__ w2,   const float* __restrict__ w1) {
    int t = blockIdx.x * blockDim.x + threadIdx.x;
    const int N2 = SN * CN * ON * DN * DN;
    const int N1 = SN * CN * ON * DN;
    if (t < N2) {
        int j = t & 15, i = (t >> 4) & 15, o = (t >> 8) & 3, c = (t >> 10) & 127, e = t >> 17;
        int tt = (o > 0);
        const float* u2 = (o == 0) ? (u2_0 + (i * 16 + j) * K2N)
                                   : (u2_1 + (((o - 1) * 16 + i) * 16 + j) * K2N);
        float acc = 0.f;
#pragma unroll
        for (int k = 0; k < K2N; k++)
            acc = fmaf(u2[k], w2[((tt * SN + e) * K2N + k) * CN + c], acc);
        g_uw2[t] = acc;
    } else if (t < N2 + N1) {
        int t2 = t - N2;
        int i = t2 & 15, o = (t2 >> 4) & 3, c = (t2 >> 6) & 127, e = t2 >> 13;
        int tt = (o > 0);
        const float* u1 = (o == 0) ? (u1_0 + i * K1N)
                                   : (u1_1 + ((o - 1) * 16 + i) * K1N);
        float acc = 0.f;
#pragma unroll
        for (int k = 0; k < K1N; k++)
            acc = fmaf(u1[k], w1[((tt * SN + e) * K1N + k) * CN + c], acc);
        g_uw1[t2] = acc;
    }
}

// ---------------- kernel 4: main contraction ----------------
// grid = SPLIT*S*C blocks; 1024 threads = (o,i,j). uw3[o,i,j,:] in 8 packed-f32x2 regs.
__global__ void __launch_bounds__(1024, 1) main_kernel(const float* __restrict__ x) {
    int bx = blockIdx.x;
    int q = bx & (SPLIT - 1);
    int pair = bx >> 2;
    int e = pair >> 7;          // pair / CN
    int c = pair & 127;         // pair % CN

    int tid = threadIdx.x;
    int o = tid >> 8, i = (tid >> 4) & 15, j = tid & 15;
    int w = tid >> 5, lane = tid & 31;

    size_t base_ec = (size_t)((e * CN + c) * ON + o);
    const ulonglong2* up = (const ulonglong2*)(g_uw3 + (base_ec * 256 + (size_t)(i * 16 + j)) * 16);
    ulonglong2 A0 = up[0], A1 = up[1], A2 = up[2], A3 = up[3];
    float uw2r = g_uw2[base_ec * 256 + i * 16 + j];
    float u1sel = (j == 0) ? g_uw1[base_ec * 16 + i] : 0.0f;

    unsigned long long vinit;
    asm("mov.b64 %0, {%1, %2};" : "=l"(vinit) : "f"(uw2r), "f"(0.0f));

    __shared__ float xs[NB][16];
    __shared__ float part[NB][33];   // padded: bank = (node + warp) & 31, conflict-free
    __shared__ int   nbs[NB];

    int cnt = g_cnt[e];
    int chunk = (cnt + SPLIT - 1) / SPLIT;
    int start = q * chunk;
    int end = start + chunk; if (end > cnt) end = cnt;
    const int* bucket = g_bucket + e * BN;

    bool b4 = (lane & 16) != 0, b3 = (lane & 8) != 0, b2 = (lane & 4) != 0;
    int node = ((lane >> 4) & 1) * 4 + ((lane >> 3) & 1) * 2 + ((lane >> 2) & 1);

    for (int nb = start; nb < end; nb += NB) {
        int rem = end - nb; if (rem > NB) rem = NB;
        __syncthreads();  // protect xs/nbs/part reuse
        if (tid < NB * 16) {
            int nn = tid >> 4, l = tid & 15;
            if (nn < rem) {
                int b = bucket[nb + nn];
                if (l == 0) nbs[nn] = b;
                xs[nn][l] = x[((size_t)b * CN + c) * 16 + l];
            }
        }
        __syncthreads();

        float contrib[NB];
#pragma unroll
        for (int nn = 0; nn < NB; nn++) {
            const ulonglong2* xv = (const ulonglong2*)xs[nn];
            ulonglong2 X0 = xv[0], X1 = xv[1], X2 = xv[2], X3 = xv[3];
            unsigned long long v = vinit;
            asm("fma.rn.f32x2 %0, %1, %2, %0;" : "+l"(v) : "l"(A0.x), "l"(X0.x));
            asm("fma.rn.f32x2 %0, %1, %2, %0;" : "+l"(v) : "l"(A0.y), "l"(X0.y));
            asm("fma.rn.f32x2 %0, %1, %2, %0;" : "+l"(v) : "l"(A1.x), "l"(X1.x));
            asm("fma.rn.f32x2 %0, %1, %2, %0;" : "+l"(v) : "l"(A1.y), "l"(X1.y));
            asm("fma.rn.f32x2 %0, %1, %2, %0;" : "+l"(v) : "l"(A2.x), "l"(X2.x));
            asm("fma.rn.f32x2 %0, %1, %2, %0;" : "+l"(v) : "l"(A2.y), "l"(X2.y));
            asm("fma.rn.f32x2 %0, %1, %2, %0;" : "+l"(v) : "l"(A3.x), "l"(X3.x));
            asm("fma.rn.f32x2 %0, %1, %2, %0;" : "+l"(v) : "l"(A3.y), "l"(X3.y));
            float vlo, vhi;
            asm("mov.b64 {%0, %1}, %2;" : "=f"(vlo), "=f"(vhi) : "l"(v));
            float vs = vlo + vhi;
            float xi = xs[nn][i], xj = xs[nn][j];
            contrib[nn] = xi * fmaf(xj, vs, u1sel);
        }

        // Multi-node butterfly: 8 independent 32-lane reductions in 9 shuffles.
        float w4[4];
#pragma unroll
        for (int k = 0; k < 4; k++) {
            float send = b4 ? contrib[k] : contrib[k + 4];
            float recv = __shfl_xor_sync(0xffffffffu, send, 16);
            w4[k] = (b4 ? contrib[k + 4] : contrib[k]) + recv;
        }
        float u2a[2];
#pragma unroll
        for (int k = 0; k < 2; k++) {
            float send = b3 ? w4[k] : w4[k + 2];
            float recv = __shfl_xor_sync(0xffffffffu, send, 8);
            u2a[k] = (b3 ? w4[k + 2] : w4[k]) + recv;
        }
        {
            float send = b2 ? u2a[0] : u2a[1];
            float recv = __shfl_xor_sync(0xffffffffu, send, 4);
            float s = (b2 ? u2a[1] : u2a[0]) + recv;
            s += __shfl_xor_sync(0xffffffffu, s, 2);
            s += __shfl_xor_sync(0xffffffffu, s, 1);
            if ((lane & 3) == 0) part[node][w] = s;
        }
        __syncthreads();

        if (tid < NB * 4) {
            int nn = tid >> 2, oo = tid & 3;
            if (nn < rem) {
                float s = 0.f;
                const float* pp = part[nn] + oo * 8;
#pragma unroll
                for (int ww = 0; ww < 8; ww++) s += pp[ww];
                g_y[((size_t)nbs[nn] * CN + c) * ON + oo] = s;
            }
        }
    }
}

// ---------------- kernel 5: equivariant linear + output flatten ----------------
__global__ void final_kernel(const float* __restrict__ w_lin, float* __restrict__ out) {
    int b = blockIdx.x;
    int s = threadIdx.x;                    // 512 threads
    __shared__ float ys[CN * ON];
    ys[s] = g_y[(size_t)b * (CN * ON) + s];
    __syncthreads();

    int t, n, oo;
    if (s < CN) { t = 0; n = s; oo = 0; }
    else {
        int r = s - CN;
        t = 1; n = r / 3; oo = 1 + (r - (r / 3) * 3);
    }
    const float* wl = w_lin + (size_t)t * CN * CN + n;
    float acc = 0.f;
#pragma unroll 8
    for (int c = 0; c < CN; c++) acc = fmaf(ys[c * ON + oo], wl[(size_t)c * CN], acc);
    out[(size_t)b * (CN * ON) + s] = acc * 0.08838834764831845f; // 1/sqrt(128)
}

// ---------------- launch ----------------
extern "C" void kernel_launch(void* const* d_in, const int* in_sizes, int n_in,
                              void* d_out, int out_size) {
    const float* x    = (const float*)d_in[0];
    const float* u3_0 = (const float*)d_in[1];
    const float* u3_1 = (const float*)d_in[2];
    const float* u2_0 = (const float*)d_in[3];
    const float* u2_1 = (const float*)d_in[4];
    const float* u1_0 = (const float*)d_in[5];
    const float* u1_1 = (const float*)d_in[6];
    const float* w3   = (const float*)d_in[7];
    const float* w2   = (const float*)d_in[8];
    const float* w1   = (const float*)d_in[9];
    const float* wlin = (const float*)d_in[10];
    const int*   sp   = (const int*)d_in[11];

    bucket_kernel<<<1, BN>>>(sp);
    uw3_kernel<<<SN * ON * DN, 256>>>(u3_0, u3_1, w3);
    {
        int total = SN * CN * ON * DN * DN + SN * CN * ON * DN;
        uw21_kernel<<<(total + 255) / 256, 256>>>(u2_0, u2_1, u1_0, u1_1, w2, w1);
    }
    main_kernel<<<SPLIT * SN * CN, 1024>>>(x);
    final_kernel<<<BN, CN * ON>>>(wlin, (float*)d_out);
}

// round 5
// speedup vs baseline: 1.6298x; 1.4259x over previous
#include <cuda_runtime.h>

#define BN 1024
#define CN 128
#define DN 16
#define SN 4
#define K3N 23
#define K2N 5
#define K1N 2
#define ON 4    // total output irrep rows: 1 (0e) + 3 (1o)
#define NB 4    // nodes per batch in main kernel
#define SPLIT 4 // node-range splits per (e,c)

// ---------------- static device scratch (no runtime allocation) ----------------
__device__ float g_uw3[(size_t)SN * CN * ON * DN * DN * DN]; // 32 MiB
__device__ float g_uw2[SN * CN * ON * DN * DN];
__device__ float g_uw1[SN * CN * ON * DN];
__device__ float g_y[(size_t)BN * CN * ON];
__device__ int   g_bucket[SN * BN];
__device__ int   g_cnt[SN];

// ---------------- kernel 1: bucket nodes by species ----------------
__global__ void bucket_kernel(const int* __restrict__ sp) {
    __shared__ int scnt[SN];
    int t = threadIdx.x;                 // exactly BN threads
    if (t < SN) scnt[t] = 0;
    __syncthreads();
    int e = sp[t];
    int pos = atomicAdd(&scnt[e], 1);
    g_bucket[e * BN + pos] = t;
    __syncthreads();
    if (t < SN) g_cnt[t] = scnt[t];
}

// ---------------- kernel 2: uw3[e,c,o,i,j,l] = sum_k u3[o,i,j,l,k] * w3[t,e,k,c] ----------------
__global__ void uw3_kernel(const float* __restrict__ u3_0,
                           const float* __restrict__ u3_1,
                           const float* __restrict__ w3) {
    int bx = blockIdx.x;
    int e = bx >> 6;
    int o = (bx >> 4) & 3;
    int i = bx & 15;
    int t = threadIdx.x;

    __shared__ float u3s[DN * DN * K3N];
    __shared__ float w3s[K3N * CN];

    const float* u3src = (o == 0)
        ? (u3_0 + (size_t)(i * DN * DN) * K3N)
        : (u3_1 + (size_t)(((o - 1) * DN + i) * DN * DN) * K3N);
    for (int idx = t; idx < DN * DN * K3N; idx += 256) u3s[idx] = u3src[idx];

    int tt = (o > 0);
    const float* w3src = w3 + (size_t)(tt * SN + e) * K3N * CN;
    for (int idx = t; idx < K3N * CN; idx += 256) w3s[idx] = w3src[idx];
    __syncthreads();

    int j = t >> 4, l = t & 15;
    float u3r[K3N];
#pragma unroll
    for (int k = 0; k < K3N; k++) u3r[k] = u3s[(j * DN + l) * K3N + k];

    int jl = (i * DN + j) * DN + l;
    for (int c = 0; c < CN; c++) {
        float acc = 0.f;
#pragma unroll
        for (int k = 0; k < K3N; k++) acc = fmaf(u3r[k], w3s[k * CN + c], acc);
        g_uw3[((size_t)((e * CN + c) * ON + o)) * (DN * DN * DN) + jl] = acc;
    }
}

// ---------------- kernel 3: uw2 / uw1 precompute ----------------
__global__ void uw21_kernel(const float* __restrict__ u2_0, const float* __restrict__ u2_1,
                            const float* __restrict__ u1_0, const float* __restrict__ u1_1,
                            const float* __restrict__ w2,   const float* __restrict__ w1) {
    int t = blockIdx.x * blockDim.x + threadIdx.x;
    const int N2 = SN * CN * ON * DN * DN;
    const int N1 = SN * CN * ON * DN;
    if (t < N2) {
        int j = t & 15, i = (t >> 4) & 15, o = (t >> 8) & 3, c = (t >> 10) & 127, e = t >> 17;
        int tt = (o > 0);
        const float* u2 = (o == 0) ? (u2_0 + (i * 16 + j) * K2N)
                                   : (u2_1 + (((o - 1) * 16 + i) * 16 + j) * K2N);
        float acc = 0.f;
#pragma unroll
        for (int k = 0; k < K2N; k++)
            acc = fmaf(u2[k], w2[((tt * SN + e) * K2N + k) * CN + c], acc);
        g_uw2[t] = acc;
    } else if (t < N2 + N1) {
        int t2 = t - N2;
        int i = t2 & 15, o = (t2 >> 4) & 3, c = (t2 >> 6) & 127, e = t2 >> 13;
        int tt = (o > 0);
        const float* u1 = (o == 0) ? (u1_0 + i * K1N)
                                   : (u1_1 + ((o - 1) * 16 + i) * K1N);
        float acc = 0.f;
#pragma unroll
        for (int k = 0; k < K1N; k++)
            acc = fmaf(u1[k], w1[((tt * SN + e) * K1N + k) * CN + c], acc);
        g_uw1[t2] = acc;
    }
}

// ---------------- kernel 4: main contraction ----------------
// grid = SPLIT*S*C blocks of 256 threads. Thread = (i,j); owns ALL 4 o-rows,
// so one x-vector load (4x LDS.128 + 2 scalar LDS) feeds 32 FFMA2.
__global__ void __launch_bounds__(256, 2) main_kernel(const float* __restrict__ x) {
    int bx = blockIdx.x;
    int q = bx & (SPLIT - 1);
    int pair = bx >> 2;
    int e = pair >> 7;          // pair / CN
    int c = pair & 127;         // pair % CN

    int tid = threadIdx.x;                 // 256 threads
    int i = (tid >> 4) & 15, j = tid & 15;
    int w = tid >> 5, lane = tid & 31;

    // uw3 rows for o = 0..3 at fixed (i,j): 64 regs of packed f32x2 pairs.
    size_t base_ec = (size_t)((e * CN + c) * ON);
    ulonglong2 A[4][4];
    unsigned long long vinit[4];
    float u1sel[4];
#pragma unroll
    for (int o = 0; o < 4; o++) {
        const ulonglong2* up = (const ulonglong2*)(g_uw3 + ((base_ec + o) * 256 + (size_t)(i * 16 + j)) * 16);
        A[o][0] = up[0]; A[o][1] = up[1]; A[o][2] = up[2]; A[o][3] = up[3];
        float uw2r = g_uw2[(base_ec + o) * 256 + i * 16 + j];
        asm("mov.b64 %0, {%1, %2};" : "=l"(vinit[o]) : "f"(uw2r), "f"(0.0f));
        u1sel[o] = (j == 0) ? g_uw1[(base_ec + o) * 16 + i] : 0.0f;
    }

    __shared__ float xs[NB][16];
    __shared__ float part[16][9];   // [m = nn*4+o][warp], pad 9 -> conflict-free
    __shared__ int   nbs[NB];

    int cnt = g_cnt[e];
    int chunk = (cnt + SPLIT - 1) / SPLIT;
    int start = q * chunk;
    int end = start + chunk; if (end > cnt) end = cnt;
    const int* bucket = g_bucket + e * BN;

    bool b4 = (lane & 16) != 0, b3 = (lane & 8) != 0, b2 = (lane & 4) != 0, b1 = (lane & 2) != 0;
    int m_idx = (b4 ? 8 : 0) + (b3 ? 4 : 0) + (b2 ? 2 : 0) + (b1 ? 1 : 0);

    for (int nb = start; nb < end; nb += NB) {
        int rem = end - nb; if (rem > NB) rem = NB;
        __syncthreads();  // protect xs/nbs/part reuse
        if (tid < NB * 16) {
            int nn = tid >> 4, l = tid & 15;
            if (nn < rem) {
                int b = bucket[nb + nn];
                if (l == 0) nbs[nn] = b;
                xs[nn][l] = x[((size_t)b * CN + c) * 16 + l];
            }
        }
        __syncthreads();

        float val[16];  // val[nn*4+o]
#pragma unroll
        for (int nn = 0; nn < NB; nn++) {
            const ulonglong2* xv = (const ulonglong2*)xs[nn];
            ulonglong2 X0 = xv[0], X1 = xv[1], X2 = xv[2], X3 = xv[3];
            float xi = xs[nn][i], xj = xs[nn][j];
#pragma unroll
            for (int o = 0; o < 4; o++) {
                unsigned long long v = vinit[o];
                asm("fma.rn.f32x2 %0, %1, %2, %0;" : "+l"(v) : "l"(A[o][0].x), "l"(X0.x));
                asm("fma.rn.f32x2 %0, %1, %2, %0;" : "+l"(v) : "l"(A[o][0].y), "l"(X0.y));
                asm("fma.rn.f32x2 %0, %1, %2, %0;" : "+l"(v) : "l"(A[o][1].x), "l"(X1.x));
                asm("fma.rn.f32x2 %0, %1, %2, %0;" : "+l"(v) : "l"(A[o][1].y), "l"(X1.y));
                asm("fma.rn.f32x2 %0, %1, %2, %0;" : "+l"(v) : "l"(A[o][2].x), "l"(X2.x));
                asm("fma.rn.f32x2 %0, %1, %2, %0;" : "+l"(v) : "l"(A[o][2].y), "l"(X2.y));
                asm("fma.rn.f32x2 %0, %1, %2, %0;" : "+l"(v) : "l"(A[o][3].x), "l"(X3.x));
                asm("fma.rn.f32x2 %0, %1, %2, %0;" : "+l"(v) : "l"(A[o][3].y), "l"(X3.y));
                float vlo, vhi;
                asm("mov.b64 {%0, %1}, %2;" : "=f"(vlo), "=f"(vhi) : "l"(v));
                float vs = vlo + vhi;
                val[nn * 4 + o] = xi * fmaf(xj, vs, u1sel[o]);
            }
        }

        // 16 independent 32-lane reductions in 16 shuffles (value-splitting butterfly).
        float v8[8];
#pragma unroll
        for (int k = 0; k < 8; k++) {
            float send = b4 ? val[k] : val[k + 8];
            float recv = __shfl_xor_sync(0xffffffffu, send, 16);
            v8[k] = (b4 ? val[k + 8] : val[k]) + recv;
        }
        float v4[4];
#pragma unroll
        for (int k = 0; k < 4; k++) {
            float send = b3 ? v8[k] : v8[k + 4];
            float recv = __shfl_xor_sync(0xffffffffu, send, 8);
            v4[k] = (b3 ? v8[k + 4] : v8[k]) + recv;
        }
        float v2[2];
#pragma unroll
        for (int k = 0; k < 2; k++) {
            float send = b2 ? v4[k] : v4[k + 2];
            float recv = __shfl_xor_sync(0xffffffffu, send, 4);
            v2[k] = (b2 ? v4[k + 2] : v4[k]) + recv;
        }
        {
            float send = b1 ? v2[0] : v2[1];
            float recv = __shfl_xor_sync(0xffffffffu, send, 2);
            float s = (b1 ? v2[1] : v2[0]) + recv;
            s += __shfl_xor_sync(0xffffffffu, s, 1);
            if ((lane & 1) == 0) part[m_idx][w] = s;
        }
        __syncthreads();

        if (tid < 16) {
            int nn = tid >> 2, oo = tid & 3;
            if (nn < rem) {
                float s = 0.f;
#pragma unroll
                for (int ww = 0; ww < 8; ww++) s += part[tid][ww];
                g_y[((size_t)nbs[nn] * CN + c) * ON + oo] = s;
            }
        }
    }
}

// ---------------- kernel 5: equivariant linear + output flatten ----------------
__global__ void final_kernel(const float* __restrict__ w_lin, float* __restrict__ out) {
    int b = blockIdx.x;
    int s = threadIdx.x;                    // 512 threads
    __shared__ float ys[CN * ON];
    ys[s] = g_y[(size_t)b * (CN * ON) + s];
    __syncthreads();

    int t, n, oo;
    if (s < CN) { t = 0; n = s; oo = 0; }
    else {
        int r = s - CN;
        t = 1; n = r / 3; oo = 1 + (r - (r / 3) * 3);
    }
    const float* wl = w_lin + (size_t)t * CN * CN + n;
    float acc = 0.f;
#pragma unroll 8
    for (int c = 0; c < CN; c++) acc = fmaf(ys[c * ON + oo], wl[(size_t)c * CN], acc);
    out[(size_t)b * (CN * ON) + s] = acc * 0.08838834764831845f; // 1/sqrt(128)
}

// ---------------- launch ----------------
extern "C" void kernel_launch(void* const* d_in, const int* in_sizes, int n_in,
                              void* d_out, int out_size) {
    const float* x    = (const float*)d_in[0];
    const float* u3_0 = (const float*)d_in[1];
    const float* u3_1 = (const float*)d_in[2];
    const float* u2_0 = (const float*)d_in[3];
    const float* u2_1 = (const float*)d_in[4];
    const float* u1_0 = (const float*)d_in[5];
    const float* u1_1 = (const float*)d_in[6];
    const float* w3   = (const float*)d_in[7];
    const float* w2   = (const float*)d_in[8];
    const float* w1   = (const float*)d_in[9];
    const float* wlin = (const float*)d_in[10];
    const int*   sp   = (const int*)d_in[11];

    bucket_kernel<<<1, BN>>>(sp);
    uw3_kernel<<<SN * ON * DN, 256>>>(u3_0, u3_1, w3);
    {
        int total = SN * CN * ON * DN * DN + SN * CN * ON * DN;
        uw21_kernel<<<(total + 255) / 256, 256>>>(u2_0, u2_1, u1_0, u1_1, w2, w1);
    }
    main_kernel<<<SPLIT * SN * CN, 256>>>(x);
    final_kernel<<<BN, CN * ON>>>(wlin, (float*)d_out);
}

// round 6
// speedup vs baseline: 3.7274x; 2.2871x over previous
#include <cuda_runtime.h>

#define BN 1024
#define CN 128
#define DN 16
#define SN 4
#define K3N 23
#define K2N 5
#define K1N 2
#define ON 4

// Stream layout per (e,c), consumed in exactly this order:
//   for i in 0..15:  [S1: 4 floats]
//     for j in i..15:  [S2: 4 floats]
//       for h in (j>>1)..7:  [8 floats: (o0l0,o0l1,o1l0,o1l1,o2l0,o2l1,o3l0,o3l1)]
// total floats = 16*4 + 136*4 + 444*8 = 4160
#define STREAMF 4160
#define NSLOTS  596   // 16 S1 + 136 S2 + 444 h-slots

// ---------------- static device scratch ----------------
__device__ float g_stream[(size_t)SN * CN * STREAMF];   // 8.5 MB
__device__ float g_y[(size_t)BN * CN * ON];
__device__ int   g_bucket[SN * BN];
__device__ int   g_cnt[SN];
__device__ int   g_sched[16];
__device__ int   g_nsched;

// ---------------- kernel 1: bucket nodes by species + chunk schedule ----------------
__global__ void bucket_kernel(const int* __restrict__ sp) {
    __shared__ int scnt[SN];
    int t = threadIdx.x;                 // exactly BN threads
    if (t < SN) scnt[t] = 0;
    __syncthreads();
    int e = sp[t];
    int pos = atomicAdd(&scnt[e], 1);
    g_bucket[e * BN + pos] = t;
    __syncthreads();
    if (t < SN) g_cnt[t] = scnt[t];
    if (t == 0) {
        int n = 0;
        for (int e2 = 0; e2 < SN; e2++)
            for (int s2 = 0; s2 < scnt[e2]; s2 += 128)
                g_sched[n++] = (e2 << 16) | s2;
        g_nsched = n;
    }
}

// ---------------- symmetrized-u helpers ----------------
__device__ __forceinline__ float u3val(int o, int i, int j, int l, int k,
                                       const float* __restrict__ u3_0,
                                       const float* __restrict__ u3_1) {
    return (o == 0) ? u3_0[((i * 16 + j) * 16 + l) * K3N + k]
                    : u3_1[((((o - 1) * 16 + i) * 16 + j) * 16 + l) * K3N + k];
}
// orbit sum over distinct permutations of sorted triple a<=b<=g
__device__ __forceinline__ float orbit3(int o, int a, int b, int g, int k,
                                        const float* __restrict__ A,
                                        const float* __restrict__ B) {
    if (a == b && b == g) return u3val(o, a, a, a, k, A, B);
    if (a == b) return u3val(o, a, a, g, k, A, B) + u3val(o, a, g, a, k, A, B) + u3val(o, g, a, a, k, A, B);
    if (b == g) return u3val(o, a, b, b, k, A, B) + u3val(o, b, a, b, k, A, B) + u3val(o, b, b, a, k, A, B);
    return u3val(o, a, b, g, k, A, B) + u3val(o, a, g, b, k, A, B) + u3val(o, b, a, g, k, A, B)
         + u3val(o, b, g, a, k, A, B) + u3val(o, g, a, b, k, A, B) + u3val(o, g, b, a, k, A, B);
}
__device__ __forceinline__ float u2val(int o, int i, int j, int k,
                                       const float* __restrict__ u2_0,
                                       const float* __restrict__ u2_1) {
    return (o == 0) ? u2_0[(i * 16 + j) * K2N + k]
                    : u2_1[(((o - 1) * 16 + i) * 16 + j) * K2N + k];
}

// ---------------- kernel 2: build coefficient stream ----------------
// grid = 4 species * 596 slots; 128 threads = channel c.
__global__ void sbuild_kernel(const float* __restrict__ u3_0, const float* __restrict__ u3_1,
                              const float* __restrict__ u2_0, const float* __restrict__ u2_1,
                              const float* __restrict__ u1_0, const float* __restrict__ u1_1,
                              const float* __restrict__ w3,   const float* __restrict__ w2,
                              const float* __restrict__ w1) {
    int e = blockIdx.x / NSLOTS;
    int slot = blockIdx.x % NSLOTS;
    int c = threadIdx.x;

    // walk the canonical stream order to locate this slot
    int s = slot, type = -1, I = 0, J = 0, H = 0, mypos = 0, pos = 0;
    for (int i = 0; i < 16 && type < 0; i++) {
        if (s == 0) { type = 0; I = i; mypos = pos; break; }
        s--; pos += 4;
        for (int j = i; j < 16; j++) {
            if (s == 0) { type = 1; I = i; J = j; mypos = pos; break; }
            s--; pos += 4;
            int nh = 8 - (j >> 1);
            if (s < nh) { type = 2; I = i; J = j; H = (j >> 1) + s; mypos = pos + s * 8; break; }
            s -= nh; pos += nh * 8;
        }
    }
    size_t base = (size_t)(e * CN + c) * STREAMF + mypos;

    if (type == 0) {            // S1: uw1[o,I]
#pragma unroll
        for (int o = 0; o < 4; o++) {
            int tt = (o > 0);
            float acc = 0.f;
#pragma unroll
            for (int k = 0; k < K1N; k++) {
                float uu = (o == 0) ? u1_0[I * K1N + k] : u1_1[((o - 1) * 16 + I) * K1N + k];
                acc = fmaf(uu, w1[((tt * SN + e) * K1N + k) * CN + c], acc);
            }
            g_stream[base + o] = acc;
        }
    } else if (type == 1) {     // S2: orbit-symmetrized uw2 for pair (I<=J)
#pragma unroll
        for (int o = 0; o < 4; o++) {
            int tt = (o > 0);
            float acc = 0.f;
#pragma unroll
            for (int k = 0; k < K2N; k++) {
                float uu = u2val(o, I, J, k, u2_0, u2_1);
                if (I < J) uu += u2val(o, J, I, k, u2_0, u2_1);
                acc = fmaf(uu, w2[((tt * SN + e) * K2N + k) * CN + c], acc);
            }
            g_stream[base + o] = acc;
        }
    } else {                    // h-slot: 8 values (4 o x 2 l), orbit-symmetrized uw3
        __shared__ float us[K3N][8];
        for (int v = threadIdx.x; v < K3N * 8; v += 128) {
            int k = v >> 3, q = v & 7;
            int o = q >> 1, dl = q & 1, l = 2 * H + dl;
            float val = 0.f;
            if (l >= J) val = orbit3(o, I, J, l, k, u3_0, u3_1);
            us[k][q] = val;
        }
        __syncthreads();
        float w3r0[K3N], w3r1[K3N];
#pragma unroll
        for (int k = 0; k < K3N; k++) {
            w3r0[k] = w3[((0 * SN + e) * K3N + k) * CN + c];
            w3r1[k] = w3[((1 * SN + e) * K3N + k) * CN + c];
        }
        float acc[8] = {0, 0, 0, 0, 0, 0, 0, 0};
#pragma unroll
        for (int k = 0; k < K3N; k++) {
            float4 a = *(const float4*)&us[k][0];
            float4 b = *(const float4*)&us[k][4];
            acc[0] = fmaf(a.x, w3r0[k], acc[0]);
            acc[1] = fmaf(a.y, w3r0[k], acc[1]);
            acc[2] = fmaf(a.z, w3r1[k], acc[2]);
            acc[3] = fmaf(a.w, w3r1[k], acc[3]);
            acc[4] = fmaf(b.x, w3r1[k], acc[4]);
            acc[5] = fmaf(b.y, w3r1[k], acc[5]);
            acc[6] = fmaf(b.z, w3r1[k], acc[6]);
            acc[7] = fmaf(b.w, w3r1[k], acc[7]);
        }
#pragma unroll
        for (int q = 0; q < 8; q++) g_stream[base + q] = acc[q];
    }
}

// ---------------- kernel 3: main contraction ----------------
// One thread per (node, channel). Block = (c, 128-node chunk of one species).
__global__ void __launch_bounds__(128, 4) main_kernel(const float* __restrict__ x) {
    __shared__ float4 st4[STREAMF / 4];
    int bx = blockIdx.x;
    int c = bx & 127;
    int chunk = bx >> 7;
    if (chunk >= g_nsched) return;
    int si = g_sched[chunk];
    int e = si >> 16, start = si & 0xffff;

    // stage this (e,c) coefficient stream into smem (coalesced)
    const float4* src = (const float4*)(g_stream + (size_t)(e * CN + c) * STREAMF);
    for (int p = threadIdx.x; p < STREAMF / 4; p += 128) st4[p] = src[p];

    int cnt = g_cnt[e];
    int idx = start + threadIdx.x;
    bool active = idx < cnt;
    int b = active ? g_bucket[e * BN + idx] : 0;

    float xv[16];
    {
        float4 z = make_float4(0.f, 0.f, 0.f, 0.f);
        float4 xr[4] = {z, z, z, z};
        if (active) {
            const float4* xp = (const float4*)(x + ((size_t)b * CN + c) * 16);
            xr[0] = xp[0]; xr[1] = xp[1]; xr[2] = xp[2]; xr[3] = xp[3];
        }
        *(float4*)&xv[0]  = xr[0];
        *(float4*)&xv[4]  = xr[1];
        *(float4*)&xv[8]  = xr[2];
        *(float4*)&xv[12] = xr[3];
    }
    unsigned long long Xp[8];
#pragma unroll
    for (int h = 0; h < 8; h++)
        asm("mov.b64 %0, {%1, %2};" : "=l"(Xp[h]) : "f"(xv[2 * h]), "f"(xv[2 * h + 1]));

    __syncthreads();
    const float* st = (const float*)st4;

    unsigned long long acc3[4] = {0ull, 0ull, 0ull, 0ull};  // packed (even-l, odd-l) sums per o
    float accs[4] = {0.f, 0.f, 0.f, 0.f};
    const float* sp = st;

#pragma unroll
    for (int i = 0; i < 16; i++) {
        float4 s1 = *(const float4*)sp; sp += 4;
        accs[0] = fmaf(s1.x, xv[i], accs[0]);
        accs[1] = fmaf(s1.y, xv[i], accs[1]);
        accs[2] = fmaf(s1.z, xv[i], accs[2]);
        accs[3] = fmaf(s1.w, xv[i], accs[3]);
#pragma unroll
        for (int j = i; j < 16; j++) {
            float p = xv[i] * xv[j];
            float4 s2 = *(const float4*)sp; sp += 4;
            accs[0] = fmaf(s2.x, p, accs[0]);
            accs[1] = fmaf(s2.y, p, accs[1]);
            accs[2] = fmaf(s2.z, p, accs[2]);
            accs[3] = fmaf(s2.w, p, accs[3]);
            unsigned long long p2;
            asm("mov.b64 %0, {%1, %1};" : "=l"(p2) : "f"(p));
#pragma unroll
            for (int h = (j >> 1); h < 8; h++) {
                unsigned long long m2;
                asm("mul.rn.f32x2 %0, %1, %2;" : "=l"(m2) : "l"(p2), "l"(Xp[h]));
                ulonglong2 qa = *(const ulonglong2*)sp;
                ulonglong2 qb = *(const ulonglong2*)(sp + 4);
                sp += 8;
                asm("fma.rn.f32x2 %0, %1, %2, %0;" : "+l"(acc3[0]) : "l"(qa.x), "l"(m2));
                asm("fma.rn.f32x2 %0, %1, %2, %0;" : "+l"(acc3[1]) : "l"(qa.y), "l"(m2));
                asm("fma.rn.f32x2 %0, %1, %2, %0;" : "+l"(acc3[2]) : "l"(qb.x), "l"(m2));
                asm("fma.rn.f32x2 %0, %1, %2, %0;" : "+l"(acc3[3]) : "l"(qb.y), "l"(m2));
            }
        }
    }

    if (active) {
        float out[4];
#pragma unroll
        for (int o = 0; o < 4; o++) {
            float lo, hi;
            asm("mov.b64 {%0, %1}, %2;" : "=f"(lo), "=f"(hi) : "l"(acc3[o]));
            out[o] = accs[o] + lo + hi;
        }
        *(float4*)(g_y + ((size_t)b * CN + c) * ON) = *(float4*)out;
    }
}

// ---------------- kernel 4: equivariant linear + output flatten ----------------
__global__ void final_kernel(const float* __restrict__ w_lin, float* __restrict__ out) {
    int b = blockIdx.x;
    int s = threadIdx.x;                    // 512 threads
    __shared__ float ys[CN * ON];
    ys[s] = g_y[(size_t)b * (CN * ON) + s];
    __syncthreads();

    int t, n, oo;
    if (s < CN) { t = 0; n = s; oo = 0; }
    else {
        int r = s - CN;
        t = 1; n = r / 3; oo = 1 + (r - (r / 3) * 3);
    }
    const float* wl = w_lin + (size_t)t * CN * CN + n;
    float acc = 0.f;
#pragma unroll 8
    for (int c = 0; c < CN; c++) acc = fmaf(ys[c * ON + oo], wl[(size_t)c * CN], acc);
    out[(size_t)b * (CN * ON) + s] = acc * 0.08838834764831845f; // 1/sqrt(128)
}

// ---------------- launch ----------------
extern "C" void kernel_launch(void* const* d_in, const int* in_sizes, int n_in,
                              void* d_out, int out_size) {
    const float* x    = (const float*)d_in[0];
    const float* u3_0 = (const float*)d_in[1];
    const float* u3_1 = (const float*)d_in[2];
    const float* u2_0 = (const float*)d_in[3];
    const float* u2_1 = (const float*)d_in[4];
    const float* u1_0 = (const float*)d_in[5];
    const float* u1_1 = (const float*)d_in[6];
    const float* w3   = (const float*)d_in[7];
    const float* w2   = (const float*)d_in[8];
    const float* w1   = (const float*)d_in[9];
    const float* wlin = (const float*)d_in[10];
    const int*   sp   = (const int*)d_in[11];

    bucket_kernel<<<1, BN>>>(sp);
    sbuild_kernel<<<SN * NSLOTS, 128>>>(u3_0, u3_1, u2_0, u2_1, u1_0, u1_1, w3, w2, w1);
    main_kernel<<<128 * 11, 128>>>(x);      // 11 = max chunks (ceil bound over species)
    final_kernel<<<BN, CN * ON>>>(wlin, (float*)d_out);
}

// round 7
// speedup vs baseline: 4.0554x; 1.0880x over previous
#include <cuda_runtime.h>

#define BN 1024
#define CN 128
#define DN 16
#define SN 4
#define K3N 23
#define K2N 5
#define K1N 2
#define ON 4

// Stream layout per (e,c), consumed in exactly this order:
//   for i in 0..15:  [S1: 4 floats]
//     for j in i..15:  [S2: 4 floats]
//       for h in (j>>1)..7:  [8 floats: (o0l0,o0l1,o1l0,o1l1,o2l0,o2l1,o3l0,o3l1)]
// total floats = 16*4 + 136*4 + 444*8 = 4160
#define STREAMF 4160
#define NSLOTS  596   // 16 S1 + 136 S2 + 444 h-slots

// ---------------- static device scratch ----------------
__device__ float g_stream[(size_t)SN * CN * STREAMF];   // 8.5 MB
__device__ float g_y[(size_t)BN * CN * ON];
__device__ int   g_bucket[SN * BN];
__device__ int   g_cnt[SN];
__device__ int   g_sched[16];
__device__ int   g_nsched;

// ---------------- kernel 1: bucket nodes by species + chunk schedule ----------------
__global__ void bucket_kernel(const int* __restrict__ sp) {
    __shared__ int scnt[SN];
    int t = threadIdx.x;                 // exactly BN threads
    if (t < SN) scnt[t] = 0;
    __syncthreads();
    int e = sp[t];
    int pos = atomicAdd(&scnt[e], 1);
    g_bucket[e * BN + pos] = t;
    __syncthreads();
    if (t < SN) g_cnt[t] = scnt[t];
    if (t == 0) {
        int n = 0;
        for (int e2 = 0; e2 < SN; e2++)
            for (int s2 = 0; s2 < scnt[e2]; s2 += 128)
                g_sched[n++] = (e2 << 16) | s2;
        g_nsched = n;
    }
}

// ---------------- symmetrized-u helpers ----------------
__device__ __forceinline__ float u3val(int o, int i, int j, int l, int k,
                                       const float* __restrict__ u3_0,
                                       const float* __restrict__ u3_1) {
    return (o == 0) ? u3_0[((i * 16 + j) * 16 + l) * K3N + k]
                    : u3_1[((((o - 1) * 16 + i) * 16 + j) * 16 + l) * K3N + k];
}
// orbit sum over distinct permutations of sorted triple a<=b<=g
__device__ __forceinline__ float orbit3(int o, int a, int b, int g, int k,
                                        const float* __restrict__ A,
                                        const float* __restrict__ B) {
    if (a == b && b == g) return u3val(o, a, a, a, k, A, B);
    if (a == b) return u3val(o, a, a, g, k, A, B) + u3val(o, a, g, a, k, A, B) + u3val(o, g, a, a, k, A, B);
    if (b == g) return u3val(o, a, b, b, k, A, B) + u3val(o, b, a, b, k, A, B) + u3val(o, b, b, a, k, A, B);
    return u3val(o, a, b, g, k, A, B) + u3val(o, a, g, b, k, A, B) + u3val(o, b, a, g, k, A, B)
         + u3val(o, b, g, a, k, A, B) + u3val(o, g, a, b, k, A, B) + u3val(o, g, b, a, k, A, B);
}
__device__ __forceinline__ float u2val(int o, int i, int j, int k,
                                       const float* __restrict__ u2_0,
                                       const float* __restrict__ u2_1) {
    return (o == 0) ? u2_0[(i * 16 + j) * K2N + k]
                    : u2_1[(((o - 1) * 16 + i) * 16 + j) * K2N + k];
}

// ---------------- kernel 2: build coefficient stream ----------------
// grid = 4 species * 596 slots; 128 threads = channel c.
__global__ void sbuild_kernel(const float* __restrict__ u3_0, const float* __restrict__ u3_1,
                              const float* __restrict__ u2_0, const float* __restrict__ u2_1,
                              const float* __restrict__ u1_0, const float* __restrict__ u1_1,
                              const float* __restrict__ w3,   const float* __restrict__ w2,
                              const float* __restrict__ w1) {
    int e = blockIdx.x / NSLOTS;
    int slot = blockIdx.x % NSLOTS;
    int c = threadIdx.x;

    // locate this slot in the canonical stream order (thread 0 only, broadcast)
    __shared__ int sinfo[5];
    if (threadIdx.x == 0) {
        int s = slot, type = -1, I = 0, J = 0, H = 0, mypos = 0, pos = 0;
        for (int i = 0; i < 16 && type < 0; i++) {
            if (s == 0) { type = 0; I = i; mypos = pos; break; }
            s--; pos += 4;
            for (int j = i; j < 16; j++) {
                if (s == 0) { type = 1; I = i; J = j; mypos = pos; break; }
                s--; pos += 4;
                int nh = 8 - (j >> 1);
                if (s < nh) { type = 2; I = i; J = j; H = (j >> 1) + s; mypos = pos + s * 8; break; }
                s -= nh; pos += nh * 8;
            }
        }
        sinfo[0] = type; sinfo[1] = I; sinfo[2] = J; sinfo[3] = H; sinfo[4] = mypos;
    }
    __syncthreads();
    int type = sinfo[0], I = sinfo[1], J = sinfo[2], H = sinfo[3], mypos = sinfo[4];
    size_t base = (size_t)(e * CN + c) * STREAMF + mypos;

    if (type == 0) {            // S1: uw1[o,I]
#pragma unroll
        for (int o = 0; o < 4; o++) {
            int tt = (o > 0);
            float acc = 0.f;
#pragma unroll
            for (int k = 0; k < K1N; k++) {
                float uu = (o == 0) ? u1_0[I * K1N + k] : u1_1[((o - 1) * 16 + I) * K1N + k];
                acc = fmaf(uu, w1[((tt * SN + e) * K1N + k) * CN + c], acc);
            }
            g_stream[base + o] = acc;
        }
    } else if (type == 1) {     // S2: orbit-symmetrized uw2 for pair (I<=J)
#pragma unroll
        for (int o = 0; o < 4; o++) {
            int tt = (o > 0);
            float acc = 0.f;
#pragma unroll
            for (int k = 0; k < K2N; k++) {
                float uu = u2val(o, I, J, k, u2_0, u2_1);
                if (I < J) uu += u2val(o, J, I, k, u2_0, u2_1);
                acc = fmaf(uu, w2[((tt * SN + e) * K2N + k) * CN + c], acc);
            }
            g_stream[base + o] = acc;
        }
    } else {                    // h-slot: 8 values (4 o x 2 l), orbit-symmetrized uw3
        __shared__ float us[K3N][8];
        for (int v = threadIdx.x; v < K3N * 8; v += 128) {
            int k = v >> 3, q = v & 7;
            int o = q >> 1, dl = q & 1, l = 2 * H + dl;
            float val = 0.f;
            if (l >= J) val = orbit3(o, I, J, l, k, u3_0, u3_1);
            us[k][q] = val;
        }
        __syncthreads();
        float w3r0[K3N], w3r1[K3N];
#pragma unroll
        for (int k = 0; k < K3N; k++) {
            w3r0[k] = w3[((0 * SN + e) * K3N + k) * CN + c];
            w3r1[k] = w3[((1 * SN + e) * K3N + k) * CN + c];
        }
        float acc[8] = {0, 0, 0, 0, 0, 0, 0, 0};
#pragma unroll
        for (int k = 0; k < K3N; k++) {
            float4 a = *(const float4*)&us[k][0];
            float4 b = *(const float4*)&us[k][4];
            acc[0] = fmaf(a.x, w3r0[k], acc[0]);
            acc[1] = fmaf(a.y, w3r0[k], acc[1]);
            acc[2] = fmaf(a.z, w3r1[k], acc[2]);
            acc[3] = fmaf(a.w, w3r1[k], acc[3]);
            acc[4] = fmaf(b.x, w3r1[k], acc[4]);
            acc[5] = fmaf(b.y, w3r1[k], acc[5]);
            acc[6] = fmaf(b.z, w3r1[k], acc[6]);
            acc[7] = fmaf(b.w, w3r1[k], acc[7]);
        }
#pragma unroll
        for (int q = 0; q < 8; q++) g_stream[base + q] = acc[q];
    }
}

// ---------------- kernel 3: main contraction ----------------
// One thread per (node, channel). Block = (c, 128-node chunk of one species).
__global__ void __launch_bounds__(128, 4) main_kernel(const float* __restrict__ x) {
    __shared__ float4 st4[STREAMF / 4];
    int bx = blockIdx.x;
    int c = bx & 127;
    int chunk = bx >> 7;
    if (chunk >= g_nsched) return;
    int si = g_sched[chunk];
    int e = si >> 16, start = si & 0xffff;

    // stage this (e,c) coefficient stream into smem (coalesced)
    const float4* src = (const float4*)(g_stream + (size_t)(e * CN + c) * STREAMF);
    for (int p = threadIdx.x; p < STREAMF / 4; p += 128) st4[p] = src[p];

    int cnt = g_cnt[e];
    int idx = start + threadIdx.x;
    bool active = idx < cnt;
    int b = active ? g_bucket[e * BN + idx] : 0;

    float xv[16];
    {
        float4 z = make_float4(0.f, 0.f, 0.f, 0.f);
        float4 xr[4] = {z, z, z, z};
        if (active) {
            const float4* xp = (const float4*)(x + ((size_t)b * CN + c) * 16);
            xr[0] = xp[0]; xr[1] = xp[1]; xr[2] = xp[2]; xr[3] = xp[3];
        }
        *(float4*)&xv[0]  = xr[0];
        *(float4*)&xv[4]  = xr[1];
        *(float4*)&xv[8]  = xr[2];
        *(float4*)&xv[12] = xr[3];
    }
    unsigned long long Xp[8];
#pragma unroll
    for (int h = 0; h < 8; h++)
        asm("mov.b64 %0, {%1, %2};" : "=l"(Xp[h]) : "f"(xv[2 * h]), "f"(xv[2 * h + 1]));

    __syncthreads();
    const float* st = (const float*)st4;

    unsigned long long acc3[4] = {0ull, 0ull, 0ull, 0ull};  // packed (even-l, odd-l) sums per o
    float accs[4] = {0.f, 0.f, 0.f, 0.f};
    const float* sp = st;

#pragma unroll
    for (int i = 0; i < 16; i++) {
        float4 s1 = *(const float4*)sp; sp += 4;
        accs[0] = fmaf(s1.x, xv[i], accs[0]);
        accs[1] = fmaf(s1.y, xv[i], accs[1]);
        accs[2] = fmaf(s1.z, xv[i], accs[2]);
        accs[3] = fmaf(s1.w, xv[i], accs[3]);
#pragma unroll
        for (int j = i; j < 16; j++) {
            float p = xv[i] * xv[j];
            float4 s2 = *(const float4*)sp; sp += 4;
            accs[0] = fmaf(s2.x, p, accs[0]);
            accs[1] = fmaf(s2.y, p, accs[1]);
            accs[2] = fmaf(s2.z, p, accs[2]);
            accs[3] = fmaf(s2.w, p, accs[3]);
            unsigned long long p2;
            asm("mov.b64 %0, {%1, %1};" : "=l"(p2) : "f"(p));
#pragma unroll
            for (int h = (j >> 1); h < 8; h++) {
                unsigned long long m2;
                asm("mul.rn.f32x2 %0, %1, %2;" : "=l"(m2) : "l"(p2), "l"(Xp[h]));
                ulonglong2 qa = *(const ulonglong2*)sp;
                ulonglong2 qb = *(const ulonglong2*)(sp + 4);
                sp += 8;
                asm("fma.rn.f32x2 %0, %1, %2, %0;" : "+l"(acc3[0]) : "l"(qa.x), "l"(m2));
                asm("fma.rn.f32x2 %0, %1, %2, %0;" : "+l"(acc3[1]) : "l"(qa.y), "l"(m2));
                asm("fma.rn.f32x2 %0, %1, %2, %0;" : "+l"(acc3[2]) : "l"(qb.x), "l"(m2));
                asm("fma.rn.f32x2 %0, %1, %2, %0;" : "+l"(acc3[3]) : "l"(qb.y), "l"(m2));
            }
        }
    }

    if (active) {
        float out[4];
#pragma unroll
        for (int o = 0; o < 4; o++) {
            float lo, hi;
            asm("mov.b64 {%0, %1}, %2;" : "=f"(lo), "=f"(hi) : "l"(acc3[o]));
            out[o] = accs[o] + lo + hi;
        }
        *(float4*)(g_y + ((size_t)b * CN + c) * ON) = *(float4*)out;
    }
}

// ---------------- kernel 4: equivariant linear, register-tiled smem GEMM ----------------
// Block = 8 nodes, 256 threads. Thread owns outputs f=2t,2t+1 (same irrep row oo)
// for all 8 nodes: 16 accumulators, 2048 FMA/thread, load:fma = 0.63.
#define NBF 8
__global__ void __launch_bounds__(256) final_kernel(const float* __restrict__ w_lin,
                                                    float* __restrict__ out) {
    __shared__ float ysm[NBF][512];      // 16 KB
    __shared__ float wsm[2][16][128];    // 16 KB, c-chunked
    int b0 = blockIdx.x * NBF;
    int tid = threadIdx.x;

    // stage y rows once (coalesced)
    {
        const float4* ysrc = (const float4*)(g_y + (size_t)b0 * 512);
        float4* ydst = (float4*)ysm;
        for (int p = tid; p < NBF * 512 / 4; p += 256) ydst[p] = ysrc[p];
    }

    int f0 = tid * 2;
    int oo = f0 >> 7;            // 0..3, same for both outputs
    int n0 = f0 & 127;           // even; second output is n0+1
    int tsel = (oo > 0) ? 1 : 0;

    float acc0[NBF], acc1[NBF];
#pragma unroll
    for (int nn = 0; nn < NBF; nn++) { acc0[nn] = 0.f; acc1[nn] = 0.f; }

    for (int chunk = 0; chunk < 8; chunk++) {
        int c0 = chunk * 16;
        __syncthreads();  // protect wsm reuse (and ysm on first pass)
        // stage wsm[t][ci][n] = w_lin[t][c0+ci][n] (coalesced float4)
        for (int p = tid; p < 2 * 16 * 128 / 4; p += 256) {
            int fi = p * 4;
            int t = fi >> 11;
            int q = fi & 2047;
            ((float4*)wsm)[p] = *(const float4*)(w_lin + (size_t)t * 16384 + c0 * 128 + q);
        }
        __syncthreads();
#pragma unroll
        for (int ci = 0; ci < 16; ci++) {
            int c = c0 + ci;
            float w0v = wsm[tsel][ci][n0];
            float w1v = wsm[tsel][ci][n0 + 1];
#pragma unroll
            for (int nn = 0; nn < NBF; nn++) {
                float yv = ysm[nn][c * 4 + oo];   // uniform per warp -> broadcast
                acc0[nn] = fmaf(yv, w0v, acc0[nn]);
                acc1[nn] = fmaf(yv, w1v, acc1[nn]);
            }
        }
    }

    const float scale = 0.08838834764831845f; // 1/sqrt(128)
    int s0 = (oo == 0) ? n0 : (128 + n0 * 3 + (oo - 1));
    int s1 = (oo == 0) ? (n0 + 1) : (128 + (n0 + 1) * 3 + (oo - 1));
#pragma unroll
    for (int nn = 0; nn < NBF; nn++) {
        out[(size_t)(b0 + nn) * 512 + s0] = acc0[nn] * scale;
        out[(size_t)(b0 + nn) * 512 + s1] = acc1[nn] * scale;
    }
}

// ---------------- launch ----------------
extern "C" void kernel_launch(void* const* d_in, const int* in_sizes, int n_in,
                              void* d_out, int out_size) {
    const float* x    = (const float*)d_in[0];
    const float* u3_0 = (const float*)d_in[1];
    const float* u3_1 = (const float*)d_in[2];
    const float* u2_0 = (const float*)d_in[3];
    const float* u2_1 = (const float*)d_in[4];
    const float* u1_0 = (const float*)d_in[5];
    const float* u1_1 = (const float*)d_in[6];
    const float* w3   = (const float*)d_in[7];
    const float* w2   = (const float*)d_in[8];
    const float* w1   = (const float*)d_in[9];
    const float* wlin = (const float*)d_in[10];
    const int*   sp   = (const int*)d_in[11];

    bucket_kernel<<<1, BN>>>(sp);
    sbuild_kernel<<<SN * NSLOTS, 128>>>(u3_0, u3_1, u2_0, u2_1, u1_0, u1_1, w3, w2, w1);
    main_kernel<<<128 * 11, 128>>>(x);      // 11 = max chunks (ceil bound over species)
    final_kernel<<<BN / NBF, 256>>>(wlin, (float*)d_out);
}